// round 1
// baseline (speedup 1.0000x reference)
#include <cuda_runtime.h>
#include <math.h>
#include <float.h>

#define N_ANCH 262144
#define NCLS   21
#define NFG    20
#define TOPK   512
#define DET    100
#define TH     0.05f
#define CLIPV  4.135166556742356f

// ---------------- scratch (static device globals; no runtime allocation) ----------------
__device__ unsigned            g_keys[NFG * N_ANCH];     // per-class sortable keys (21 MB)
__device__ unsigned            g_hist[NFG * 4096];
__device__ unsigned            g_pivot[NFG];
__device__ unsigned            g_collcnt[NFG];
__device__ unsigned long long  g_coll[NFG * 4096];
__device__ float               g_vals[NFG * TOPK];
__device__ float               g_boxes[NFG * TOPK * 7];
__device__ float4              g_nmsA[NFG * TOPK];       // xlo,xhi,ylo,yhi
__device__ float4              g_nmsB[NFG * TOPK];       // zlo,zhi,vol,-
__device__ unsigned            g_mask[NFG * TOPK * 16];  // 512-bit IoU>thresh rows
__device__ float               g_flat[NFG * TOPK];

// ---------------- K0: reset per-replay state ----------------
__global__ void k_zero() {
    int i = blockIdx.x * blockDim.x + threadIdx.x;
    if (i < NFG * 4096) g_hist[i] = 0u;
    if (i < NFG)        g_collcnt[i] = 0u;
}

// ---------------- K1: softmax -> per-class keys ----------------
__global__ void k_softmax(const float* __restrict__ logits) {
    int n = blockIdx.x * blockDim.x + threadIdx.x;
    if (n >= N_ANCH) return;
    const float* row = logits + (size_t)n * NCLS;
    float v[NCLS];
    float m = -FLT_MAX;
#pragma unroll
    for (int c = 0; c < NCLS; c++) { v[c] = row[c]; m = fmaxf(m, v[c]); }
    float s = 0.f;
#pragma unroll
    for (int c = 0; c < NCLS; c++) { v[c] = expf(v[c] - m); s += v[c]; }
#pragma unroll
    for (int c = 1; c < NCLS; c++) {
        float p = v[c] / s;
        unsigned key = (p > TH) ? __float_as_uint(p) : 0u;   // positive floats: bits order == value order
        g_keys[(size_t)(c - 1) * N_ANCH + n] = key;
    }
}

// ---------------- K2: per-class 4096-bin histogram (top 12 bits) ----------------
__global__ void k_hist() {
    __shared__ unsigned h[4096];
    int c = blockIdx.x, chunk = blockIdx.y, tid = threadIdx.x;
    for (int i = tid; i < 4096; i += 256) h[i] = 0u;
    __syncthreads();
    size_t base = (size_t)c * N_ANCH + (size_t)chunk * 4096;
    for (int i = tid; i < 4096; i += 256) atomicAdd(&h[g_keys[base + i] >> 20], 1u);
    __syncthreads();
    for (int i = tid; i < 4096; i += 256) {
        unsigned cnt = h[i];
        if (cnt) atomicAdd(&g_hist[c * 4096 + i], cnt);
    }
}

// ---------------- K3: find pivot bin (bin containing the 512th largest) ----------------
__global__ void k_pivot() {
    __shared__ unsigned seg[256];
    int c = blockIdx.x, tid = threadIdx.x;
    unsigned s = 0;
    for (int b = 0; b < 16; b++) s += g_hist[c * 4096 + tid * 16 + b];
    seg[tid] = s;
    __syncthreads();
    if (tid == 0) {
        unsigned cum = 0; int t = 255;
        for (; t >= 0; t--) { if (cum + seg[t] >= TOPK) break; cum += seg[t]; }
        unsigned pivot = 0;
        if (t >= 0) {
            for (int b = t * 16 + 15; b >= t * 16; b--) {
                cum += g_hist[c * 4096 + b];
                if (cum >= TOPK) { pivot = (unsigned)b; break; }
            }
        }
        g_pivot[c] = pivot;
    }
}

// ---------------- K4: collect keys in bins >= pivot ----------------
__global__ void k_collect() {
    int c = blockIdx.x, chunk = blockIdx.y, tid = threadIdx.x;
    unsigned pv = g_pivot[c];
    size_t base = (size_t)c * N_ANCH + (size_t)chunk * 4096;
    unsigned nbase = (unsigned)chunk * 4096u;
    for (int i = tid; i < 4096; i += 256) {
        unsigned k = g_keys[base + i];
        if (k != 0u && (k >> 20) >= pv) {
            unsigned p = atomicAdd(&g_collcnt[c], 1u);
            if (p < 4096u)
                g_coll[c * 4096 + p] =
                    ((unsigned long long)k << 32) | (unsigned long long)(0xFFFFFFFFu - (nbase + (unsigned)i));
        }
    }
}

// ---------------- K5: per-class bitonic sort (desc) + decode ----------------
__global__ void k_sortdecode(const float* __restrict__ br, const float* __restrict__ cb) {
    __shared__ unsigned long long s[4096];
    int c = blockIdx.x, tid = threadIdx.x;  // 512 threads
    unsigned m = g_collcnt[c]; if (m > 4096u) m = 4096u;
    for (int i = tid; i < 4096; i += 512) s[i] = (i < (int)m) ? g_coll[c * 4096 + i] : 0ull;
    __syncthreads();
    for (int k = 2; k <= 4096; k <<= 1)
        for (int j = k >> 1; j > 0; j >>= 1) {
            for (int i = tid; i < 4096; i += 512) {
                int l = i ^ j;
                if (l > i) {
                    unsigned long long a = s[i], b = s[l];
                    bool sw = ((i & k) == 0) ? (a < b) : (a > b);  // overall descending
                    if (sw) { s[i] = b; s[l] = a; }
                }
            }
            __syncthreads();
        }
    // top-512 -> decode
    unsigned long long key = s[tid];
    unsigned hb  = (unsigned)(key >> 32);
    unsigned idx = 0xFFFFFFFFu - (unsigned)key;
    float val;
    if (hb) val = __uint_as_float(hb);
    else { val = -INFINITY; if (idx >= N_ANCH) idx = 0u; }
    const float* p = cb + (size_t)idx * 7;
    float px = p[0], py = p[1], pzb = p[2], psx = p[3], psy = p[4], psz = p[5], pry = p[6];
    const float* d = br + (size_t)idx * (NCLS * 7) + (size_t)(c + 1) * 7;
    float dx = d[0] / 10.0f, dy = d[1] / 10.0f, dz = d[2] / 10.0f;
    float dsx = fminf(d[3] / 5.0f, CLIPV);
    float dsy = fminf(d[4] / 5.0f, CLIPV);
    float dsz = fminf(d[5] / 5.0f, CLIPV);
    float pcz = pzb + psz * 0.5f;
    float cx = px + dx * psx;
    float cy = py + dy * psy;
    float cz = pcz + dz * psz;
    float sx = psx * expf(dsx);
    float sy = psy * expf(dsy);
    float sz = psz * expf(dsz);
    float ry = pry + d[6];
    float zb = cz - sz * 0.5f;
    int o = c * TOPK + tid;
    float* bx = g_boxes + (size_t)o * 7;
    bx[0] = cx; bx[1] = cy; bx[2] = zb; bx[3] = sx; bx[4] = sy; bx[5] = sz; bx[6] = ry;
    g_vals[o] = val;
    g_nmsA[o] = make_float4(cx - sx * 0.5f, cx + sx * 0.5f, cy - sy * 0.5f, cy + sy * 0.5f);
    g_nmsB[o] = make_float4(zb, zb + sz, sx * sy * sz, 0.f);
}

// ---------------- K6: IoU suppression bitmask build (grid 20x8) ----------------
__global__ void k_mask() {
    __shared__ float4 A[512], B[512];
    int c = blockIdx.x, sl = blockIdx.y, tid = threadIdx.x;  // 512 threads
    A[tid] = g_nmsA[c * 512 + tid];
    B[tid] = g_nmsB[c * 512 + tid];
    __syncthreads();
    int r = tid >> 3, sub = tid & 7;
    int i = sl * 64 + r;
    float4 a = A[i], b = B[i];
    unsigned w0 = 0u, w1 = 0u;
    int j0 = sub * 64;
    for (int jj = 0; jj < 64; jj++) {
        int j = j0 + jj;
        float4 ca = A[j], cb4 = B[j];
        float ox = fmaxf(fminf(a.y, ca.y) - fmaxf(a.x, ca.x), 0.f);
        float oy = fmaxf(fminf(a.w, ca.w) - fmaxf(a.z, ca.z), 0.f);
        float oz = fmaxf(fminf(b.y, cb4.y) - fmaxf(b.x, cb4.x), 0.f);
        float inter = ox * oy * oz;
        float den = b.z + cb4.z - inter + 1e-7f;
        if (inter > 0.5f * den) {            // == iou > 0.5 (den > 0), avoids fp32 div
            if (jj < 32) w0 |= 1u << jj; else w1 |= 1u << (jj - 32);
        }
    }
    g_mask[(c * 512 + i) * 16 + sub * 2]     = w0;
    g_mask[(c * 512 + i) * 16 + sub * 2 + 1] = w1;
}

// ---------------- K7: sequential greedy NMS scan (one warp per class) ----------------
__global__ void k_nmsscan() {
    __shared__ unsigned msk[512 * 16];
    __shared__ unsigned validw[16];
    __shared__ unsigned keepw_sh[16];
    int c = blockIdx.x, tid = threadIdx.x;  // 512 threads
    for (int i = tid; i < 8192; i += 512) msk[i] = g_mask[c * 8192 + i];
    bool v = g_vals[c * 512 + tid] > TH;
    unsigned bal = __ballot_sync(0xffffffffu, v);
    if ((tid & 31) == 0) validw[tid >> 5] = bal;
    __syncthreads();
    if (tid < 32) {
        unsigned keep = 0u;
        int lane = tid;
        for (int i = 0; i < 512; i++) {
            unsigned mw = (lane < 16) ? msk[i * 16 + lane] : 0u;
            bool sup = __any_sync(0xffffffffu, (mw & keep) != 0u);
            bool vv = (validw[i >> 5] >> (i & 31)) & 1u;
            bool k = vv && !sup;
            if (k && lane == (i >> 5)) keep |= 1u << (i & 31);
        }
        if (lane < 16) keepw_sh[lane] = keep;
    }
    __syncthreads();
    unsigned kb = (keepw_sh[tid >> 5] >> (tid & 31)) & 1u;
    g_flat[c * 512 + tid] = kb ? g_vals[c * 512 + tid] : -1e9f;
}

// ---------------- K8: global top-100 (2-level radix select + small bitonic) ----------------
__global__ void k_top(float* __restrict__ out) {
    __shared__ unsigned sk[NFG * TOPK];   // 10240 transformed keys (40 KB)
    __shared__ unsigned hist[256];
    __shared__ unsigned long long coll[512];
    __shared__ unsigned collc;
    __shared__ int s_pb1, s_pb2;
    __shared__ unsigned s_ab1;
    int tid = threadIdx.x;  // 1024 threads
    for (int i = tid; i < NFG * TOPK; i += 1024) {
        unsigned u = __float_as_uint(g_flat[i]);
        sk[i] = (u & 0x80000000u) ? ~u : (u | 0x80000000u);  // order-preserving transform
    }
    if (tid < 256) hist[tid] = 0u;
    if (tid == 0) collc = 0u;
    __syncthreads();
    for (int i = tid; i < NFG * TOPK; i += 1024) atomicAdd(&hist[sk[i] >> 24], 1u);
    __syncthreads();
    if (tid == 0) {
        unsigned cum = 0; int b = 255;
        for (; b >= 0; b--) { cum += hist[b]; if (cum >= DET) break; }
        if (b < 0) b = 0;
        s_pb1 = b; s_ab1 = cum - hist[b];
    }
    __syncthreads();
    int pb1 = s_pb1; unsigned ab1 = s_ab1;
    if (tid < 256) hist[tid] = 0u;
    __syncthreads();
    for (int i = tid; i < NFG * TOPK; i += 1024) {
        unsigned k = sk[i];
        if ((int)(k >> 24) == pb1) atomicAdd(&hist[(k >> 16) & 0xFFu], 1u);
    }
    __syncthreads();
    if (tid == 0) {
        unsigned cum = ab1; int b = 255;
        for (; b >= 0; b--) { cum += hist[b]; if (cum >= DET) break; }
        if (b < 0) b = 0;
        s_pb2 = b;
    }
    __syncthreads();
    unsigned thr = ((unsigned)pb1 << 8) | (unsigned)s_pb2;
    for (int i = tid; i < NFG * TOPK; i += 1024) {
        unsigned k = sk[i];
        if ((k >> 16) >= thr) {
            unsigned p = atomicAdd(&collc, 1u);
            if (p < 512u)
                coll[p] = ((unsigned long long)k << 32) | (unsigned long long)(0xFFFFFFFFu - (unsigned)i);
        }
    }
    __syncthreads();
    unsigned m = collc; if (m > 512u) m = 512u;
    if (tid < 512 && tid >= (int)m) coll[tid] = 0ull;
    __syncthreads();
    for (int k = 2; k <= 512; k <<= 1)
        for (int j = k >> 1; j > 0; j >>= 1) {
            if (tid < 512) {
                int i = tid, l = i ^ j;
                if (l > i) {
                    unsigned long long A = coll[i], Bq = coll[l];
                    bool sw = ((i & k) == 0) ? (A < Bq) : (A > Bq);
                    if (sw) { coll[i] = Bq; coll[l] = A; }
                }
            }
            __syncthreads();
        }
    if (tid < DET) {
        unsigned long long kk = coll[tid];
        unsigned idx = 0xFFFFFFFFu - (unsigned)kk;
        if (idx >= NFG * TOPK) idx = 0u;
        const float* bx = g_boxes + (size_t)idx * 7;
        float* o = out + tid * 9;
        o[0] = bx[0]; o[1] = bx[1]; o[2] = bx[2]; o[3] = bx[3];
        o[4] = bx[4]; o[5] = bx[5]; o[6] = bx[6];
        o[7] = g_flat[idx];
        o[8] = (float)((idx >> 9) + 1);
    }
}

// ---------------- launch ----------------
extern "C" void kernel_launch(void* const* d_in, const int* in_sizes, int n_in,
                              void* d_out, int out_size) {
    const float* logits = (const float*)d_in[0];
    const float* br     = (const float*)d_in[1];
    const float* cb     = (const float*)d_in[2];
    float* out = (float*)d_out;

    k_zero<<<(NFG * 4096 + 255) / 256, 256>>>();
    k_softmax<<<N_ANCH / 256, 256>>>(logits);
    dim3 gh(NFG, 64);
    k_hist<<<gh, 256>>>();
    k_pivot<<<NFG, 256>>>();
    k_collect<<<gh, 256>>>();
    k_sortdecode<<<NFG, 512>>>(br, cb);
    dim3 gm(NFG, 8);
    k_mask<<<gm, 512>>>();
    k_nmsscan<<<NFG, 512>>>();
    k_top<<<1, 1024>>>(out);
    (void)in_sizes; (void)n_in; (void)out_size;
}

// round 3
// speedup vs baseline: 1.8455x; 1.8455x over previous
#include <cuda_runtime.h>
#include <math.h>
#include <float.h>

#define N_ANCH 262144
#define NCLS   21
#define NFG    20
#define TOPK   512
#define DET    100
#define TH     0.05f
#define CLIPV  4.135166556742356f
#define NBIN   288
#define BINOFF 0x1EA6u   // bits(0.05f) >> 17

// ---------------- scratch (static device globals; zero-initialized at load) ----------------
__device__ unsigned            g_keys[NFG * N_ANCH];     // per-class sortable keys (21 MB)
__device__ unsigned            g_hist[NFG * NBIN];       // fine histogram (zeroed by k_top tail)
__device__ unsigned            g_collcnt[NFG];           // (zeroed by k_top tail)
__device__ unsigned long long  g_coll[NFG * 4096];
__device__ float               g_vals[NFG * TOPK];
__device__ float               g_boxes[NFG * TOPK * 7];
__device__ float4              g_nmsA[NFG * TOPK];       // xlo,xhi,ylo,yhi
__device__ float4              g_nmsB[NFG * TOPK];       // zlo,zhi,vol,-
__device__ unsigned            g_mask[NFG * TOPK * 16];  // 512-bit IoU>thresh rows
__device__ float               g_flat[NFG * TOPK];

// FMA-pipe exp: exp(x) = 2^(x*log2e), magic-number rounding + deg-7 poly of 2^f.
// No MUFU, no CVT. Rel err ~1e-7 for |x| <= 20.
__device__ __forceinline__ float fexp(float x) {
    const float L2E = 1.4426950408889634f;
    x = fmaxf(x, -80.0f);
    float r  = fmaf(x, L2E, 12582912.0f);             // 1.5*2^23 magic round
    int   ii = __float_as_int(r) - 0x4B400000;
    float fi = r - 12582912.0f;
    float f  = fmaf(x, L2E, -fi);                     // f in ~[-0.5, 0.5]
    float p  = 1.52527338e-5f;
    p = fmaf(p, f, 1.54035304e-4f);
    p = fmaf(p, f, 1.33335581e-3f);
    p = fmaf(p, f, 9.61812911e-3f);
    p = fmaf(p, f, 5.55041087e-2f);
    p = fmaf(p, f, 2.40226507e-1f);
    p = fmaf(p, f, 6.93147181e-1f);
    p = fmaf(p, f, 1.0f);
    return p * __int_as_float((ii + 127) << 23);
}

// ---------------- K1: fused softmax -> keys + per-class histogram ----------------
// grid 256 blocks x 256 threads, 4 chunks of 256 anchors each.
// static smem: hist[20*288] (23040 B) + stage[256*21 floats] (21504 B) = 44544 B < 48 KB
__global__ void __launch_bounds__(256) k_smx(const float* __restrict__ logits) {
    __shared__ unsigned hist[NFG * NBIN];
    __shared__ float    stage[256 * NCLS];
    int tid = threadIdx.x;
    for (int i = tid; i < NFG * NBIN; i += 256) hist[i] = 0u;
    __syncthreads();
    for (int ch = 0; ch < 4; ch++) {
        int base = blockIdx.x * 1024 + ch * 256;
        const float4* src = (const float4*)(logits + (size_t)base * NCLS);  // base%4==0 -> 16B aligned
        float4* dst = (float4*)stage;
#pragma unroll
        for (int i = 0; i < 6; i++) {
            int idx = tid + i * 256;
            if (idx < 1344) dst[idx] = src[idx];           // 256 rows * 21 floats = 1344 float4
        }
        __syncthreads();
        int n = base + tid;
        const float* row = stage + tid * NCLS;             // stride 21 (odd) -> conflict-free
        float e[NCLS];
        float s = 0.f;
#pragma unroll
        for (int c = 0; c < NCLS; c++) { e[c] = fexp(row[c]); s += e[c]; }
        float rs = __fdividef(1.0f, s);
#pragma unroll
        for (int c = 1; c < NCLS; c++) {
            float p = e[c] * rs;
            unsigned key = (p > TH) ? __float_as_uint(p) : 0u;  // positive floats: bit order == value order
            g_keys[(size_t)(c - 1) * N_ANCH + n] = key;
            if (key) {
                unsigned b = (key >> 17) - BINOFF;
                if (b >= NBIN) b = NBIN - 1;               // safety clamp (analytically in-range)
                atomicAdd(&hist[(c - 1) * NBIN + b], 1u);
            }
        }
        __syncthreads();
    }
    for (int i = tid; i < NFG * NBIN; i += 256) {
        unsigned v = hist[i];
        if (v) atomicAdd(&g_hist[i], v);
    }
}

// ---------------- K2: pivot (per block, from hist) + collect keys >= pivot bin ----------------
__global__ void __launch_bounds__(256) k_collect() {
    __shared__ unsigned sh[NBIN];
    __shared__ unsigned s_thr;
    int c = blockIdx.x, tid = threadIdx.x;
    for (int i = tid; i < NBIN; i += 256) sh[i] = g_hist[c * NBIN + i];
    __syncthreads();
    if (tid == 0) {
        unsigned cum = 0, pv = 0;
        for (int b = NBIN - 1; b >= 0; b--) { cum += sh[b]; if (cum >= TOPK) { pv = (unsigned)b; break; } }
        s_thr = (pv + BINOFF) << 17;                       // key >= thr  <=>  bin >= pivot
    }
    __syncthreads();
    unsigned thr = s_thr;
    size_t base = (size_t)c * N_ANCH + (size_t)blockIdx.y * 4096;
    const uint4* kp = (const uint4*)(g_keys + base);       // 16KB-aligned chunks
    unsigned ibase = blockIdx.y * 4096u;
    for (int i = tid; i < 1024; i += 256) {
        uint4 k4 = kp[i];
        unsigned ks[4] = {k4.x, k4.y, k4.z, k4.w};
#pragma unroll
        for (int l = 0; l < 4; l++) {
            unsigned k = ks[l];
            if (k >= thr) {
                unsigned p = atomicAdd(&g_collcnt[c], 1u);
                if (p < 4096u)
                    g_coll[c * 4096 + p] =
                        ((unsigned long long)k << 32) |
                        (unsigned long long)(0xFFFFFFFFu - (ibase + (unsigned)i * 4u + (unsigned)l));
            }
        }
    }
}

// ---------------- K3: per-class bitonic sort (desc, dynamic size) + decode ----------------
__global__ void __launch_bounds__(512) k_sortdecode(const float* __restrict__ br, const float* __restrict__ cb) {
    __shared__ unsigned long long s[4096];
    int c = blockIdx.x, tid = threadIdx.x;  // 512 threads
    unsigned m = g_collcnt[c]; if (m > 4096u) m = 4096u;
    int S = 512; while (S < (int)m) S <<= 1;               // uniform across block
    for (int i = tid; i < S; i += 512) s[i] = (i < (int)m) ? g_coll[c * 4096 + i] : 0ull;
    __syncthreads();
    for (int k = 2; k <= S; k <<= 1)
        for (int j = k >> 1; j > 0; j >>= 1) {
            for (int i = tid; i < S; i += 512) {
                int l = i ^ j;
                if (l > i) {
                    unsigned long long a = s[i], b = s[l];
                    bool sw = ((i & k) == 0) ? (a < b) : (a > b);  // overall descending
                    if (sw) { s[i] = b; s[l] = a; }
                }
            }
            __syncthreads();
        }
    // top-512 -> decode
    unsigned long long key = s[tid];
    unsigned hb  = (unsigned)(key >> 32);
    unsigned idx = 0xFFFFFFFFu - (unsigned)key;
    float val;
    if (hb) val = __uint_as_float(hb);
    else { val = -INFINITY; if (idx >= N_ANCH) idx = 0u; }
    const float* p = cb + (size_t)idx * 7;
    float px = p[0], py = p[1], pzb = p[2], psx = p[3], psy = p[4], psz = p[5], pry = p[6];
    const float* d = br + (size_t)idx * (NCLS * 7) + (size_t)(c + 1) * 7;
    float dx = d[0] / 10.0f, dy = d[1] / 10.0f, dz = d[2] / 10.0f;
    float dsx = fminf(d[3] / 5.0f, CLIPV);
    float dsy = fminf(d[4] / 5.0f, CLIPV);
    float dsz = fminf(d[5] / 5.0f, CLIPV);
    float pcz = pzb + psz * 0.5f;
    float cx = px + dx * psx;
    float cy = py + dy * psy;
    float cz = pcz + dz * psz;
    float sx = psx * expf(dsx);
    float sy = psy * expf(dsy);
    float sz = psz * expf(dsz);
    float ry = pry + d[6];
    float zb = cz - sz * 0.5f;
    int o = c * TOPK + tid;
    float* bx = g_boxes + (size_t)o * 7;
    bx[0] = cx; bx[1] = cy; bx[2] = zb; bx[3] = sx; bx[4] = sy; bx[5] = sz; bx[6] = ry;
    g_vals[o] = val;
    g_nmsA[o] = make_float4(cx - sx * 0.5f, cx + sx * 0.5f, cy - sy * 0.5f, cy + sy * 0.5f);
    g_nmsB[o] = make_float4(zb, zb + sz, sx * sy * sz, 0.f);
}

// ---------------- K4: triangular IoU bitmask, interleaved rows for load balance ----------------
// grid (20,16), 512 threads. row i = (tid>>4)*16 + blockIdx.y; word sub = tid&15.
// Only words with j0 <= i computed (scan consumes j < i); others written 0.
__global__ void __launch_bounds__(512) k_mask() {
    __shared__ float4 A[512], B[512];
    int c = blockIdx.x, ph = blockIdx.y, tid = threadIdx.x;
    A[tid] = g_nmsA[c * 512 + tid];
    B[tid] = g_nmsB[c * 512 + tid];
    __syncthreads();
    int r = tid >> 4;
    int i = r * 16 + ph;
    int sub = tid & 15;
    int j0 = sub * 32;
    unsigned w = 0u;
    if (j0 <= i) {
        float4 a = A[i], b = B[i];
#pragma unroll 4
        for (int jj = 0; jj < 32; jj++) {
            float4 ca = A[j0 + jj], cb4 = B[j0 + jj];
            float ox = fmaxf(fminf(a.y, ca.y) - fmaxf(a.x, ca.x), 0.f);
            float oy = fmaxf(fminf(a.w, ca.w) - fmaxf(a.z, ca.z), 0.f);
            float oz = fmaxf(fminf(b.y, cb4.y) - fmaxf(b.x, cb4.x), 0.f);
            float inter = ox * oy * oz;
            float den = b.z + cb4.z - inter + 1e-7f;
            if (inter > 0.5f * den) w |= 1u << jj;         // == iou > 0.5 without fp32 div
        }
    }
    g_mask[(c * 512 + i) * 16 + sub] = w;
}

// ---------------- K5: sequential greedy NMS scan (one warp per class) ----------------
__global__ void __launch_bounds__(512) k_nmsscan() {
    __shared__ unsigned msk[512 * 16];
    __shared__ unsigned validw[16];
    __shared__ unsigned keepw_sh[16];
    int c = blockIdx.x, tid = threadIdx.x;
    for (int i = tid; i < 8192; i += 512) msk[i] = g_mask[c * 8192 + i];
    bool v = g_vals[c * 512 + tid] > TH;
    unsigned bal = __ballot_sync(0xffffffffu, v);
    if ((tid & 31) == 0) validw[tid >> 5] = bal;
    __syncthreads();
    if (tid < 32) {
        unsigned keep = 0u;
        int lane = tid;
        for (int i = 0; i < 512; i++) {
            unsigned mw = (lane < 16) ? msk[i * 16 + lane] : 0u;
            bool sup = __any_sync(0xffffffffu, (mw & keep) != 0u);
            bool vv = (validw[i >> 5] >> (i & 31)) & 1u;
            bool k = vv && !sup;
            if (k && lane == (i >> 5)) keep |= 1u << (i & 31);
        }
        if (lane < 16) keepw_sh[lane] = keep;
    }
    __syncthreads();
    unsigned kb = (keepw_sh[tid >> 5] >> (tid & 31)) & 1u;
    g_flat[c * 512 + tid] = kb ? g_vals[c * 512 + tid] : -1e9f;
}

// ---------------- K6: global top-100 + zero state for next replay ----------------
__global__ void __launch_bounds__(1024) k_top(float* __restrict__ out) {
    __shared__ unsigned sk[NFG * TOPK];
    __shared__ unsigned hist[256];
    __shared__ unsigned long long coll[512];
    __shared__ unsigned collc;
    __shared__ int s_pb1, s_pb2;
    __shared__ unsigned s_ab1;
    int tid = threadIdx.x;
    for (int i = tid; i < NFG * TOPK; i += 1024) {
        unsigned u = __float_as_uint(g_flat[i]);
        sk[i] = (u & 0x80000000u) ? ~u : (u | 0x80000000u);
    }
    if (tid < 256) hist[tid] = 0u;
    if (tid == 0) collc = 0u;
    __syncthreads();
    for (int i = tid; i < NFG * TOPK; i += 1024) atomicAdd(&hist[sk[i] >> 24], 1u);
    __syncthreads();
    if (tid == 0) {
        unsigned cum = 0; int b = 255;
        for (; b >= 0; b--) { cum += hist[b]; if (cum >= DET) break; }
        if (b < 0) b = 0;
        s_pb1 = b; s_ab1 = cum - hist[b];
    }
    __syncthreads();
    int pb1 = s_pb1; unsigned ab1 = s_ab1;
    if (tid < 256) hist[tid] = 0u;
    __syncthreads();
    for (int i = tid; i < NFG * TOPK; i += 1024) {
        unsigned k = sk[i];
        if ((int)(k >> 24) == pb1) atomicAdd(&hist[(k >> 16) & 0xFFu], 1u);
    }
    __syncthreads();
    if (tid == 0) {
        unsigned cum = ab1; int b = 255;
        for (; b >= 0; b--) { cum += hist[b]; if (cum >= DET) break; }
        if (b < 0) b = 0;
        s_pb2 = b;
    }
    __syncthreads();
    unsigned thr = ((unsigned)pb1 << 8) | (unsigned)s_pb2;
    for (int i = tid; i < NFG * TOPK; i += 1024) {
        unsigned k = sk[i];
        if ((k >> 16) >= thr) {
            unsigned p = atomicAdd(&collc, 1u);
            if (p < 512u)
                coll[p] = ((unsigned long long)k << 32) | (unsigned long long)(0xFFFFFFFFu - (unsigned)i);
        }
    }
    __syncthreads();
    unsigned m = collc; if (m > 512u) m = 512u;
    if (tid < 512 && tid >= (int)m) coll[tid] = 0ull;
    __syncthreads();
    for (int k = 2; k <= 512; k <<= 1)
        for (int j = k >> 1; j > 0; j >>= 1) {
            if (tid < 512) {
                int i = tid, l = i ^ j;
                if (l > i) {
                    unsigned long long A = coll[i], Bq = coll[l];
                    bool sw = ((i & k) == 0) ? (A < Bq) : (A > Bq);
                    if (sw) { coll[i] = Bq; coll[l] = A; }
                }
            }
            __syncthreads();
        }
    if (tid < DET) {
        unsigned long long kk = coll[tid];
        unsigned idx = 0xFFFFFFFFu - (unsigned)kk;
        if (idx >= NFG * TOPK) idx = 0u;
        const float* bx = g_boxes + (size_t)idx * 7;
        float* o = out + tid * 9;
        o[0] = bx[0]; o[1] = bx[1]; o[2] = bx[2]; o[3] = bx[3];
        o[4] = bx[4]; o[5] = bx[5]; o[6] = bx[6];
        o[7] = g_flat[idx];
        o[8] = (float)((idx >> 9) + 1);
    }
    // zero state for the next graph replay (globals start zeroed at load,
    // so every execution must also end zeroed)
    for (int i = tid; i < NFG * NBIN; i += 1024) g_hist[i] = 0u;
    if (tid < NFG) g_collcnt[tid] = 0u;
}

// ---------------- launch ----------------
extern "C" void kernel_launch(void* const* d_in, const int* in_sizes, int n_in,
                              void* d_out, int out_size) {
    const float* logits = (const float*)d_in[0];
    const float* br     = (const float*)d_in[1];
    const float* cb     = (const float*)d_in[2];
    float* out = (float*)d_out;

    k_smx<<<256, 256>>>(logits);
    dim3 gc(NFG, 64);
    k_collect<<<gc, 256>>>();
    k_sortdecode<<<NFG, 512>>>(br, cb);
    dim3 gm(NFG, 16);
    k_mask<<<gm, 512>>>();
    k_nmsscan<<<NFG, 512>>>();
    k_top<<<1, 1024>>>(out);
    (void)in_sizes; (void)n_in; (void)out_size;
}

// round 5
// speedup vs baseline: 1.9036x; 1.0315x over previous
#include <cuda_runtime.h>
#include <math.h>
#include <float.h>

#define N_ANCH 262144
#define NCLS   21
#define NFG    20
#define TOPK   512
#define DET    100
#define TH     0.05f
#define CLIPV  4.135166556742356f
#define NBIN   288
#define BINOFF 0x1EA6u   // bits(0.05f) >> 17

// ---------------- scratch (static device globals; zero-initialized at load) ----------------
__device__ unsigned            g_keys[NFG * N_ANCH];     // per-class sortable keys (21 MB)
__device__ unsigned            g_hist[NFG * NBIN];       // histogram (re-zeroed by k_top tail)
__device__ unsigned            g_collcnt[NFG];           // (re-zeroed by k_top tail)
__device__ unsigned long long  g_coll[NFG * 4096];
__device__ float               g_vals[NFG * TOPK];
__device__ float               g_boxes[NFG * TOPK * 7];
__device__ float4              g_nmsA[NFG * TOPK];       // xlo,xhi,ylo,yhi
__device__ float4              g_nmsB[NFG * TOPK];       // zlo,zhi,vol,-
__device__ float               g_flat[NFG * TOPK];

// FMA-pipe exp: exp(x) = 2^(x*log2e), magic-number rounding + deg-7 poly of 2^f.
__device__ __forceinline__ float fexp(float x) {
    const float L2E = 1.4426950408889634f;
    x = fmaxf(x, -80.0f);
    float r  = fmaf(x, L2E, 12582912.0f);             // 1.5*2^23 magic round
    int   ii = __float_as_int(r) - 0x4B400000;
    float fi = r - 12582912.0f;
    float f  = fmaf(x, L2E, -fi);                     // f in ~[-0.5, 0.5]
    float p  = 1.52527338e-5f;
    p = fmaf(p, f, 1.54035304e-4f);
    p = fmaf(p, f, 1.33335581e-3f);
    p = fmaf(p, f, 9.61812911e-3f);
    p = fmaf(p, f, 5.55041087e-2f);
    p = fmaf(p, f, 2.40226507e-1f);
    p = fmaf(p, f, 6.93147181e-1f);
    p = fmaf(p, f, 1.0f);
    return p * __int_as_float((ii + 127) << 23);
}

// ---------------- K1: fused softmax -> keys + per-class histogram ----------------
__global__ void __launch_bounds__(256) k_smx(const float* __restrict__ logits) {
    __shared__ unsigned hist[NFG * NBIN];
    __shared__ float    stage[256 * NCLS];
    int tid = threadIdx.x;
    for (int i = tid; i < NFG * NBIN; i += 256) hist[i] = 0u;
    __syncthreads();
    for (int ch = 0; ch < 4; ch++) {
        int base = blockIdx.x * 1024 + ch * 256;
        const float4* src = (const float4*)(logits + (size_t)base * NCLS);
        float4* dst = (float4*)stage;
#pragma unroll
        for (int i = 0; i < 6; i++) {
            int idx = tid + i * 256;
            if (idx < 1344) dst[idx] = src[idx];           // 256*21 floats = 1344 float4
        }
        __syncthreads();
        int n = base + tid;
        const float* row = stage + tid * NCLS;             // stride 21 -> conflict-free
        float e[NCLS];
        float s = 0.f;
#pragma unroll
        for (int c = 0; c < NCLS; c++) { e[c] = fexp(row[c]); s += e[c]; }
        float rs = __fdividef(1.0f, s);
#pragma unroll
        for (int c = 1; c < NCLS; c++) {
            float p = e[c] * rs;
            unsigned key = (p > TH) ? __float_as_uint(p) : 0u;
            g_keys[(size_t)(c - 1) * N_ANCH + n] = key;
            if (key) {
                unsigned b = (key >> 17) - BINOFF;
                if (b >= NBIN) b = NBIN - 1;
                atomicAdd(&hist[(c - 1) * NBIN + b], 1u);
            }
        }
        __syncthreads();
    }
    for (int i = tid; i < NFG * NBIN; i += 256) {
        unsigned v = hist[i];
        if (v) atomicAdd(&g_hist[i], v);
    }
}

// ---------------- K2: pivot + collect keys >= pivot bin ----------------
__global__ void __launch_bounds__(256) k_collect() {
    __shared__ unsigned sh[NBIN];
    __shared__ unsigned s_thr;
    int c = blockIdx.x, tid = threadIdx.x;
    for (int i = tid; i < NBIN; i += 256) sh[i] = g_hist[c * NBIN + i];
    __syncthreads();
    if (tid == 0) {
        unsigned cum = 0, pv = 0;
        for (int b = NBIN - 1; b >= 0; b--) { cum += sh[b]; if (cum >= TOPK) { pv = (unsigned)b; break; } }
        s_thr = (pv + BINOFF) << 17;
    }
    __syncthreads();
    unsigned thr = s_thr;
    size_t base = (size_t)c * N_ANCH + (size_t)blockIdx.y * 4096;
    const uint4* kp = (const uint4*)(g_keys + base);
    unsigned ibase = blockIdx.y * 4096u;
    for (int i = tid; i < 1024; i += 256) {
        uint4 k4 = kp[i];
        unsigned ks[4] = {k4.x, k4.y, k4.z, k4.w};
#pragma unroll
        for (int l = 0; l < 4; l++) {
            unsigned k = ks[l];
            if (k >= thr) {
                unsigned p = atomicAdd(&g_collcnt[c], 1u);
                if (p < 4096u)
                    g_coll[c * 4096 + p] =
                        ((unsigned long long)k << 32) |
                        (unsigned long long)(0xFFFFFFFFu - (ibase + (unsigned)i * 4u + (unsigned)l));
            }
        }
    }
}

// ---------------- K3: per-class bitonic sort (desc, dynamic size) + decode ----------------
__global__ void __launch_bounds__(512) k_sortdecode(const float* __restrict__ br, const float* __restrict__ cb) {
    __shared__ unsigned long long s[4096];
    int c = blockIdx.x, tid = threadIdx.x;
    unsigned m = g_collcnt[c]; if (m > 4096u) m = 4096u;
    int S = 512; while (S < (int)m) S <<= 1;
    for (int i = tid; i < S; i += 512) s[i] = (i < (int)m) ? g_coll[c * 4096 + i] : 0ull;
    __syncthreads();
    for (int k = 2; k <= S; k <<= 1)
        for (int j = k >> 1; j > 0; j >>= 1) {
            for (int i = tid; i < S; i += 512) {
                int l = i ^ j;
                if (l > i) {
                    unsigned long long a = s[i], b = s[l];
                    bool sw = ((i & k) == 0) ? (a < b) : (a > b);
                    if (sw) { s[i] = b; s[l] = a; }
                }
            }
            __syncthreads();
        }
    unsigned long long key = s[tid];
    unsigned hb  = (unsigned)(key >> 32);
    unsigned idx = 0xFFFFFFFFu - (unsigned)key;
    float val;
    if (hb) val = __uint_as_float(hb);
    else { val = -INFINITY; if (idx >= N_ANCH) idx = 0u; }
    const float* p = cb + (size_t)idx * 7;
    float px = p[0], py = p[1], pzb = p[2], psx = p[3], psy = p[4], psz = p[5], pry = p[6];
    const float* d = br + (size_t)idx * (NCLS * 7) + (size_t)(c + 1) * 7;
    float dx = d[0] / 10.0f, dy = d[1] / 10.0f, dz = d[2] / 10.0f;
    float dsx = fminf(d[3] / 5.0f, CLIPV);
    float dsy = fminf(d[4] / 5.0f, CLIPV);
    float dsz = fminf(d[5] / 5.0f, CLIPV);
    float pcz = pzb + psz * 0.5f;
    float cx = px + dx * psx;
    float cy = py + dy * psy;
    float cz = pcz + dz * psz;
    float sx = psx * expf(dsx);
    float sy = psy * expf(dsy);
    float sz = psz * expf(dsz);
    float ry = pry + d[6];
    float zb = cz - sz * 0.5f;
    int o = c * TOPK + tid;
    float* bx = g_boxes + (size_t)o * 7;
    bx[0] = cx; bx[1] = cy; bx[2] = zb; bx[3] = sx; bx[4] = sy; bx[5] = sz; bx[6] = ry;
    g_vals[o] = val;
    g_nmsA[o] = make_float4(cx - sx * 0.5f, cx + sx * 0.5f, cy - sy * 0.5f, cy + sy * 0.5f);
    g_nmsB[o] = make_float4(zb, zb + sz, sx * sy * sz, 0.f);
}

// ---------------- K4: fused IoU mask build + greedy NMS scan (1 block/class) ----------------
// Mask build: warp-task (w, r), r >= w (136 tasks over 16 warps). Lane = candidate j
// = w*32+lane (registers); warp sweeps rows i in chunk r with broadcast LDS; word via ballot.
// Triangular shared mask: row i (chunk q=i>>5) words at base = 32*q(q+1)/2 + (i&31)*(q+1).
__global__ void __launch_bounds__(512) k_nms() {
    __shared__ float4  A[512];       // xlo,xhi,ylo,yhi
    __shared__ float2  Bz[512];      // zlo,zhi
    __shared__ float   Vol[512];
    __shared__ unsigned tri[4352];   // triangular mask words
    __shared__ unsigned validw[16], keepw[16];
    int c = blockIdx.x, tid = threadIdx.x, lane = tid & 31, wid = tid >> 5;
    float4 a4 = g_nmsA[c * 512 + tid];
    float4 b4 = g_nmsB[c * 512 + tid];
    float  val = g_vals[c * 512 + tid];
    A[tid]   = a4;
    Bz[tid]  = make_float2(b4.x, b4.y);
    Vol[tid] = b4.z;
    unsigned bal = __ballot_sync(0xffffffffu, val > TH);
    if (lane == 0) validw[wid] = bal;
    __syncthreads();

    for (int t = wid; t < 136; t += 16) {
        int w = 0, t2 = t;
        while (t2 >= 16 - w) { t2 -= 16 - w; w++; }   // uniform within warp
        int r = w + t2;
        int j = w * 32 + lane;
        float4 ca   = A[j];                            // consecutive lanes: conflict-free
        float2 cz   = Bz[j];
        float  cvol = Vol[j];
        unsigned base_r = 32u * ((unsigned)(r * (r + 1)) >> 1);
        int i0 = r * 32;
#pragma unroll 4
        for (int ii = 0; ii < 32; ii++) {
            int i = i0 + ii;
            float4 a  = A[i];                          // broadcast
            float2 az = Bz[i];
            float  av = Vol[i];
            float ox = fmaxf(fminf(a.y, ca.y) - fmaxf(a.x, ca.x), 0.f);
            float oy = fmaxf(fminf(a.w, ca.w) - fmaxf(a.z, ca.z), 0.f);
            float oz = fmaxf(fminf(az.y, cz.y) - fmaxf(az.x, cz.x), 0.f);
            float inter = ox * oy * oz;
            float den = av + cvol - inter + 1e-7f;
            unsigned wbits = __ballot_sync(0xffffffffu, inter > 0.5f * den);
            if (lane == 0) tri[base_r + (unsigned)ii * (unsigned)(r + 1) + (unsigned)w] = wbits;
        }
    }
    __syncthreads();

    if (wid == 0) {
        unsigned keep = 0u;                            // lane L holds keep bits for rows L*32..L*32+31
        for (int i = 0; i < 512; i++) {
            int q = i >> 5;
            unsigned base = 32u * ((unsigned)(q * (q + 1)) >> 1) + (unsigned)(i & 31) * (unsigned)(q + 1);
            unsigned mw = (lane <= q) ? tri[base + lane] : 0u;
            bool sup = __any_sync(0xffffffffu, (mw & keep) != 0u);
            bool vv = (validw[q] >> (i & 31)) & 1u;
            bool k = vv && !sup;
            if (k && lane == q) keep |= 1u << (i & 31);
        }
        if (lane < 16) keepw[lane] = keep;
    }
    __syncthreads();
    unsigned kb = (keepw[wid] >> lane) & 1u;
    g_flat[c * 512 + tid] = kb ? val : -1e9f;
}

// ---------------- K5: global top-100 + zero state for next replay ----------------
__global__ void __launch_bounds__(1024) k_top(float* __restrict__ out) {
    __shared__ unsigned sk[NFG * TOPK];
    __shared__ unsigned hist[256];
    __shared__ unsigned long long coll[512];
    __shared__ unsigned collc;
    __shared__ int s_pb1, s_pb2;
    __shared__ unsigned s_ab1;
    int tid = threadIdx.x;
    for (int i = tid; i < NFG * TOPK; i += 1024) {
        unsigned u = __float_as_uint(g_flat[i]);
        sk[i] = (u & 0x80000000u) ? ~u : (u | 0x80000000u);
    }
    if (tid < 256) hist[tid] = 0u;
    if (tid == 0) collc = 0u;
    __syncthreads();
    for (int i = tid; i < NFG * TOPK; i += 1024) atomicAdd(&hist[sk[i] >> 24], 1u);
    __syncthreads();
    if (tid == 0) {
        unsigned cum = 0; int b = 255;
        for (; b >= 0; b--) { cum += hist[b]; if (cum >= DET) break; }
        if (b < 0) b = 0;
        s_pb1 = b; s_ab1 = cum - hist[b];
    }
    __syncthreads();
    int pb1 = s_pb1; unsigned ab1 = s_ab1;
    if (tid < 256) hist[tid] = 0u;
    __syncthreads();
    for (int i = tid; i < NFG * TOPK; i += 1024) {
        unsigned k = sk[i];
        if ((int)(k >> 24) == pb1) atomicAdd(&hist[(k >> 16) & 0xFFu], 1u);
    }
    __syncthreads();
    if (tid == 0) {
        unsigned cum = ab1; int b = 255;
        for (; b >= 0; b--) { cum += hist[b]; if (cum >= DET) break; }
        if (b < 0) b = 0;
        s_pb2 = b;
    }
    __syncthreads();
    unsigned thr = ((unsigned)pb1 << 8) | (unsigned)s_pb2;
    for (int i = tid; i < NFG * TOPK; i += 1024) {
        unsigned k = sk[i];
        if ((k >> 16) >= thr) {
            unsigned p = atomicAdd(&collc, 1u);
            if (p < 512u)
                coll[p] = ((unsigned long long)k << 32) | (unsigned long long)(0xFFFFFFFFu - (unsigned)i);
        }
    }
    __syncthreads();
    unsigned m = collc; if (m > 512u) m = 512u;
    if (tid < 512 && tid >= (int)m) coll[tid] = 0ull;
    __syncthreads();
    for (int k = 2; k <= 512; k <<= 1)
        for (int j = k >> 1; j > 0; j >>= 1) {
            if (tid < 512) {
                int i = tid, l = i ^ j;
                if (l > i) {
                    unsigned long long A = coll[i], Bq = coll[l];
                    bool sw = ((i & k) == 0) ? (A < Bq) : (A > Bq);
                    if (sw) { coll[i] = Bq; coll[l] = A; }
                }
            }
            __syncthreads();
        }
    if (tid < DET) {
        unsigned long long kk = coll[tid];
        unsigned idx = 0xFFFFFFFFu - (unsigned)kk;
        if (idx >= NFG * TOPK) idx = 0u;
        const float* bx = g_boxes + (size_t)idx * 7;
        float* o = out + tid * 9;
        o[0] = bx[0]; o[1] = bx[1]; o[2] = bx[2]; o[3] = bx[3];
        o[4] = bx[4]; o[5] = bx[5]; o[6] = bx[6];
        o[7] = g_flat[idx];
        o[8] = (float)((idx >> 9) + 1);
    }
    for (int i = tid; i < NFG * NBIN; i += 1024) g_hist[i] = 0u;
    if (tid < NFG) g_collcnt[tid] = 0u;
}

// ---------------- launch ----------------
extern "C" void kernel_launch(void* const* d_in, const int* in_sizes, int n_in,
                              void* d_out, int out_size) {
    const float* logits = (const float*)d_in[0];
    const float* br     = (const float*)d_in[1];
    const float* cb     = (const float*)d_in[2];
    float* out = (float*)d_out;

    k_smx<<<256, 256>>>(logits);
    dim3 gc(NFG, 64);
    k_collect<<<gc, 256>>>();
    k_sortdecode<<<NFG, 512>>>(br, cb);
    k_nms<<<NFG, 512>>>();
    k_top<<<1, 1024>>>(out);
    (void)in_sizes; (void)n_in; (void)out_size;
}

// round 6
// speedup vs baseline: 2.5943x; 1.3628x over previous
#include <cuda_runtime.h>
#include <math.h>
#include <float.h>

#define N_ANCH 262144
#define NCLS   21
#define NFG    20
#define TOPK   512
#define DET    100
#define TH     0.05f
#define CLIPV  4.135166556742356f
#define NBIN   288
#define BINOFF 0x1EA6u   // bits(0.05f) >> 17
#define TRIW   4352      // triangular words per class: sum_{r=0..15} 32*(r+1)

// ---------------- scratch (static device globals; zero-initialized at load) ----------------
__device__ unsigned            g_keys[NFG * N_ANCH];     // per-class sortable keys (21 MB)
__device__ unsigned            g_hist[NFG * NBIN];       // histogram (re-zeroed by k_top tail)
__device__ unsigned            g_collcnt[NFG];           // (re-zeroed by k_top tail)
__device__ unsigned long long  g_coll[NFG * 4096];
__device__ float               g_vals[NFG * TOPK];
__device__ float               g_boxes[NFG * TOPK * 7];
__device__ float4              g_nmsA[NFG * TOPK];       // xlo,xhi,ylo,yhi
__device__ float4              g_nmsB[NFG * TOPK];       // zlo,zhi,vol,-
__device__ unsigned            g_tri[NFG * TRIW];        // triangular IoU words
__device__ float               g_flat[NFG * TOPK];

// FMA-pipe exp: exp(x) = 2^(x*log2e), magic-number rounding + deg-7 poly of 2^f.
__device__ __forceinline__ float fexp(float x) {
    const float L2E = 1.4426950408889634f;
    x = fmaxf(x, -80.0f);
    float r  = fmaf(x, L2E, 12582912.0f);
    int   ii = __float_as_int(r) - 0x4B400000;
    float fi = r - 12582912.0f;
    float f  = fmaf(x, L2E, -fi);
    float p  = 1.52527338e-5f;
    p = fmaf(p, f, 1.54035304e-4f);
    p = fmaf(p, f, 1.33335581e-3f);
    p = fmaf(p, f, 9.61812911e-3f);
    p = fmaf(p, f, 5.55041087e-2f);
    p = fmaf(p, f, 2.40226507e-1f);
    p = fmaf(p, f, 6.93147181e-1f);
    p = fmaf(p, f, 1.0f);
    return p * __int_as_float((ii + 127) << 23);
}

// ---------------- K1: fused softmax -> keys + per-class histogram ----------------
__global__ void __launch_bounds__(256) k_smx(const float* __restrict__ logits) {
    __shared__ unsigned hist[NFG * NBIN];
    __shared__ float    stage[256 * NCLS];
    int tid = threadIdx.x;
    for (int i = tid; i < NFG * NBIN; i += 256) hist[i] = 0u;
    __syncthreads();
    for (int ch = 0; ch < 4; ch++) {
        int base = blockIdx.x * 1024 + ch * 256;
        const float4* src = (const float4*)(logits + (size_t)base * NCLS);
        float4* dst = (float4*)stage;
#pragma unroll
        for (int i = 0; i < 6; i++) {
            int idx = tid + i * 256;
            if (idx < 1344) dst[idx] = src[idx];
        }
        __syncthreads();
        int n = base + tid;
        const float* row = stage + tid * NCLS;
        float e[NCLS];
        float s = 0.f;
#pragma unroll
        for (int c = 0; c < NCLS; c++) { e[c] = fexp(row[c]); s += e[c]; }
        float rs = __fdividef(1.0f, s);
#pragma unroll
        for (int c = 1; c < NCLS; c++) {
            float p = e[c] * rs;
            unsigned key = (p > TH) ? __float_as_uint(p) : 0u;
            g_keys[(size_t)(c - 1) * N_ANCH + n] = key;
            if (key) {
                unsigned b = (key >> 17) - BINOFF;
                if (b >= NBIN) b = NBIN - 1;
                atomicAdd(&hist[(c - 1) * NBIN + b], 1u);
            }
        }
        __syncthreads();
    }
    for (int i = tid; i < NFG * NBIN; i += 256) {
        unsigned v = hist[i];
        if (v) atomicAdd(&g_hist[i], v);
    }
}

// ---------------- K2: pivot + collect keys >= pivot bin ----------------
__global__ void __launch_bounds__(256) k_collect() {
    __shared__ unsigned sh[NBIN];
    __shared__ unsigned s_thr;
    int c = blockIdx.x, tid = threadIdx.x;
    for (int i = tid; i < NBIN; i += 256) sh[i] = g_hist[c * NBIN + i];
    __syncthreads();
    if (tid == 0) {
        unsigned cum = 0, pv = 0;
        for (int b = NBIN - 1; b >= 0; b--) { cum += sh[b]; if (cum >= TOPK) { pv = (unsigned)b; break; } }
        s_thr = (pv + BINOFF) << 17;
    }
    __syncthreads();
    unsigned thr = s_thr;
    size_t base = (size_t)c * N_ANCH + (size_t)blockIdx.y * 4096;
    const uint4* kp = (const uint4*)(g_keys + base);
    unsigned ibase = blockIdx.y * 4096u;
    for (int i = tid; i < 1024; i += 256) {
        uint4 k4 = kp[i];
        unsigned ks[4] = {k4.x, k4.y, k4.z, k4.w};
#pragma unroll
        for (int l = 0; l < 4; l++) {
            unsigned k = ks[l];
            if (k >= thr) {
                unsigned p = atomicAdd(&g_collcnt[c], 1u);
                if (p < 4096u)
                    g_coll[c * 4096 + p] =
                        ((unsigned long long)k << 32) |
                        (unsigned long long)(0xFFFFFFFFu - (ibase + (unsigned)i * 4u + (unsigned)l));
            }
        }
    }
}

// ---------------- K3: per-class bitonic sort (desc, dynamic size) + decode ----------------
__global__ void __launch_bounds__(512) k_sortdecode(const float* __restrict__ br, const float* __restrict__ cb) {
    __shared__ unsigned long long s[4096];
    int c = blockIdx.x, tid = threadIdx.x;
    unsigned m = g_collcnt[c]; if (m > 4096u) m = 4096u;
    int S = 512; while (S < (int)m) S <<= 1;
    for (int i = tid; i < S; i += 512) s[i] = (i < (int)m) ? g_coll[c * 4096 + i] : 0ull;
    __syncthreads();
    for (int k = 2; k <= S; k <<= 1)
        for (int j = k >> 1; j > 0; j >>= 1) {
            for (int i = tid; i < S; i += 512) {
                int l = i ^ j;
                if (l > i) {
                    unsigned long long a = s[i], b = s[l];
                    bool sw = ((i & k) == 0) ? (a < b) : (a > b);
                    if (sw) { s[i] = b; s[l] = a; }
                }
            }
            __syncthreads();
        }
    unsigned long long key = s[tid];
    unsigned hb  = (unsigned)(key >> 32);
    unsigned idx = 0xFFFFFFFFu - (unsigned)key;
    float val;
    if (hb) val = __uint_as_float(hb);
    else { val = -INFINITY; if (idx >= N_ANCH) idx = 0u; }
    const float* p = cb + (size_t)idx * 7;
    float px = p[0], py = p[1], pzb = p[2], psx = p[3], psy = p[4], psz = p[5], pry = p[6];
    const float* d = br + (size_t)idx * (NCLS * 7) + (size_t)(c + 1) * 7;
    float dx = d[0] / 10.0f, dy = d[1] / 10.0f, dz = d[2] / 10.0f;
    float dsx = fminf(d[3] / 5.0f, CLIPV);
    float dsy = fminf(d[4] / 5.0f, CLIPV);
    float dsz = fminf(d[5] / 5.0f, CLIPV);
    float pcz = pzb + psz * 0.5f;
    float cx = px + dx * psx;
    float cy = py + dy * psy;
    float cz = pcz + dz * psz;
    float sx = psx * expf(dsx);
    float sy = psy * expf(dsy);
    float sz = psz * expf(dsz);
    float ry = pry + d[6];
    float zb = cz - sz * 0.5f;
    int o = c * TOPK + tid;
    float* bx = g_boxes + (size_t)o * 7;
    bx[0] = cx; bx[1] = cy; bx[2] = zb; bx[3] = sx; bx[4] = sy; bx[5] = sz; bx[6] = ry;
    g_vals[o] = val;
    g_nmsA[o] = make_float4(cx - sx * 0.5f, cx + sx * 0.5f, cy - sy * 0.5f, cy + sy * 0.5f);
    g_nmsB[o] = make_float4(zb, zb + sz, sx * sy * sz, 0.f);
}

// ---------------- K4: IoU mask build, lane-per-row, no ballots ----------------
// grid (20, 9), 512 thr. Warp task t = by*16+wid in [0,136): (w, r) with r >= w.
// Lane = row i = r*32+lane; serial over j = w*32+jj via broadcast LDS; register OR word.
// Word stored at tri base(i) + w; diag word (w==r) includes self bit (masked by scan).
__global__ void __launch_bounds__(512) k_mask2() {
    __shared__ float4 P1[512], P2[512];
    int c = blockIdx.x, tid = threadIdx.x, lane = tid & 31, wid = tid >> 5;
    P1[tid] = g_nmsA[c * 512 + tid];
    P2[tid] = g_nmsB[c * 512 + tid];
    __syncthreads();
    int t = blockIdx.y * 16 + wid;
    if (t < 136) {
        int w = 0, t2 = t;
        while (t2 >= 16 - w) { t2 -= 16 - w; w++; }   // warp-uniform
        int r = w + t2;
        int i = r * 32 + lane;
        float4 a = P1[i];                              // consecutive lanes: conflict-free
        float4 b = P2[i];
        unsigned word = 0u;
        int j0 = w * 32;
#pragma unroll 8
        for (int jj = 0; jj < 32; jj++) {
            float4 ca = P1[j0 + jj];                   // broadcast
            float4 cb = P2[j0 + jj];
            float ox = fmaxf(fminf(a.y, ca.y) - fmaxf(a.x, ca.x), 0.f);
            float oy = fmaxf(fminf(a.w, ca.w) - fmaxf(a.z, ca.z), 0.f);
            float oz = fmaxf(fminf(b.y, cb.y) - fmaxf(b.x, cb.x), 0.f);
            float inter = ox * oy * oz;
            float den = b.z + cb.z - inter + 1e-7f;
            if (inter > 0.5f * den) word |= 1u << jj;  // == iou > 0.5 without div
        }
        unsigned base = 32u * ((unsigned)(r * (r + 1)) >> 1)
                      + (unsigned)lane * (unsigned)(r + 1) + (unsigned)w;
        g_tri[c * TRIW + base] = word;
    }
}

// ---------------- K5: chunked greedy NMS scan, fast path for conflict-free chunks ----------------
// 20 blocks x 32 threads. Lane = row-in-chunk. Greedy keep == iterative selection.
__global__ void __launch_bounds__(32) k_scan() {
    __shared__ unsigned tri[TRIW];
    __shared__ unsigned keepw[16];
    int c = blockIdx.x, lane = threadIdx.x;
    {   // coalesced triangular-mask load
        const uint4* src = (const uint4*)(g_tri + c * TRIW);
        uint4* dst = (uint4*)tri;
        for (int i = lane; i < TRIW / 4; i += 32) dst[i] = src[i];
    }
    float    vals[16];
    unsigned validw[16];
#pragma unroll
    for (int w = 0; w < 16; w++) {
        vals[w] = g_vals[c * 512 + w * 32 + lane];
        validw[w] = __ballot_sync(0xffffffffu, vals[w] > TH);
    }
    __syncwarp();
    for (int q = 0; q < 16; q++) {
        unsigned base = 32u * ((unsigned)(q * (q + 1)) >> 1) + (unsigned)lane * (unsigned)(q + 1);
        unsigned sup = 0u;
        for (int w = 0; w < q; w++) sup |= tri[base + w] & keepw[w];
        unsigned diag = tri[base + q] & ((1u << lane) - 1u);   // strictly-lower same-chunk bits
        unsigned alive = validw[q] & ~__ballot_sync(0xffffffffu, sup != 0u);
        unsigned conflict = __ballot_sync(0xffffffffu, (diag & alive) != 0u);
        unsigned kc;
        if (conflict == 0u) {
            kc = alive;                                         // no intra-chunk suppression possible
        } else {
            kc = 0u; unsigned rem = alive;                      // frontier loop (warp-uniform state)
            while (rem) {
                unsigned ii = (unsigned)__ffs(rem) - 1u;
                kc |= 1u << ii;
                rem &= ~(1u << ii);
                bool supn = (diag >> ii) & 1u;                  // my row overlapped by kept ii
                rem &= ~__ballot_sync(0xffffffffu, supn);
            }
        }
        if (lane == 0) keepw[q] = kc;
        __syncwarp();
    }
#pragma unroll
    for (int w = 0; w < 16; w++) {
        bool k = (keepw[w] >> lane) & 1u;
        g_flat[c * 512 + w * 32 + lane] = k ? vals[w] : -1e9f;
    }
}

// ---------------- K6: global top-100 + zero state for next replay ----------------
__global__ void __launch_bounds__(1024) k_top(float* __restrict__ out) {
    __shared__ unsigned sk[NFG * TOPK];
    __shared__ unsigned hist[256];
    __shared__ unsigned long long coll[512];
    __shared__ unsigned collc;
    __shared__ int s_pb1, s_pb2;
    __shared__ unsigned s_ab1;
    int tid = threadIdx.x;
    for (int i = tid; i < NFG * TOPK; i += 1024) {
        unsigned u = __float_as_uint(g_flat[i]);
        sk[i] = (u & 0x80000000u) ? ~u : (u | 0x80000000u);
    }
    if (tid < 256) hist[tid] = 0u;
    if (tid == 0) collc = 0u;
    __syncthreads();
    for (int i = tid; i < NFG * TOPK; i += 1024) atomicAdd(&hist[sk[i] >> 24], 1u);
    __syncthreads();
    if (tid == 0) {
        unsigned cum = 0; int b = 255;
        for (; b >= 0; b--) { cum += hist[b]; if (cum >= DET) break; }
        if (b < 0) b = 0;
        s_pb1 = b; s_ab1 = cum - hist[b];
    }
    __syncthreads();
    int pb1 = s_pb1; unsigned ab1 = s_ab1;
    if (tid < 256) hist[tid] = 0u;
    __syncthreads();
    for (int i = tid; i < NFG * TOPK; i += 1024) {
        unsigned k = sk[i];
        if ((int)(k >> 24) == pb1) atomicAdd(&hist[(k >> 16) & 0xFFu], 1u);
    }
    __syncthreads();
    if (tid == 0) {
        unsigned cum = ab1; int b = 255;
        for (; b >= 0; b--) { cum += hist[b]; if (cum >= DET) break; }
        if (b < 0) b = 0;
        s_pb2 = b;
    }
    __syncthreads();
    unsigned thr = ((unsigned)pb1 << 8) | (unsigned)s_pb2;
    for (int i = tid; i < NFG * TOPK; i += 1024) {
        unsigned k = sk[i];
        if ((k >> 16) >= thr) {
            unsigned p = atomicAdd(&collc, 1u);
            if (p < 512u)
                coll[p] = ((unsigned long long)k << 32) | (unsigned long long)(0xFFFFFFFFu - (unsigned)i);
        }
    }
    __syncthreads();
    unsigned m = collc; if (m > 512u) m = 512u;
    if (tid < 512 && tid >= (int)m) coll[tid] = 0ull;
    __syncthreads();
    for (int k = 2; k <= 512; k <<= 1)
        for (int j = k >> 1; j > 0; j >>= 1) {
            if (tid < 512) {
                int i = tid, l = i ^ j;
                if (l > i) {
                    unsigned long long A = coll[i], Bq = coll[l];
                    bool sw = ((i & k) == 0) ? (A < Bq) : (A > Bq);
                    if (sw) { coll[i] = Bq; coll[l] = A; }
                }
            }
            __syncthreads();
        }
    if (tid < DET) {
        unsigned long long kk = coll[tid];
        unsigned idx = 0xFFFFFFFFu - (unsigned)kk;
        if (idx >= NFG * TOPK) idx = 0u;
        const float* bx = g_boxes + (size_t)idx * 7;
        float* o = out + tid * 9;
        o[0] = bx[0]; o[1] = bx[1]; o[2] = bx[2]; o[3] = bx[3];
        o[4] = bx[4]; o[5] = bx[5]; o[6] = bx[6];
        o[7] = g_flat[idx];
        o[8] = (float)((idx >> 9) + 1);
    }
    for (int i = tid; i < NFG * NBIN; i += 1024) g_hist[i] = 0u;
    if (tid < NFG) g_collcnt[tid] = 0u;
}

// ---------------- launch ----------------
extern "C" void kernel_launch(void* const* d_in, const int* in_sizes, int n_in,
                              void* d_out, int out_size) {
    const float* logits = (const float*)d_in[0];
    const float* br     = (const float*)d_in[1];
    const float* cb     = (const float*)d_in[2];
    float* out = (float*)d_out;

    k_smx<<<256, 256>>>(logits);
    dim3 gc(NFG, 64);
    k_collect<<<gc, 256>>>();
    k_sortdecode<<<NFG, 512>>>(br, cb);
    dim3 gm(NFG, 9);
    k_mask2<<<gm, 512>>>();
    k_scan<<<NFG, 32>>>();
    k_top<<<1, 1024>>>(out);
    (void)in_sizes; (void)n_in; (void)out_size;
}